// round 5
// baseline (speedup 1.0000x reference)
#include <cuda_runtime.h>
#include <math.h>

// ---------------------------------------------------------------------------
// NeuralODE on GB300 (round 5): latency-focused.
//  * 256 CTAs x 512 threads, 4 rows/CTA, 1 CTA/SM -> LPT via longest-first
//  * layer-2 k-quarter split: W2r = 16 packed f32x2 regs/thread,
//    butterfly shfl xor8+xor16 reduce; h1 stored kq-interleaved (bank-clean)
//  * rows counting-sorted by length; CTA skips evals past its max t_end
//  * fma.rn.f32x2 / add.rn.f32x2 hot path, MUFU tanh.approx
// ---------------------------------------------------------------------------

#define Bsz   1024
#define Tn    128
#define Dn    256
#define NACT  9
#define LATD  32
#define INW   43
#define RR    4      // rows per CTA
#define NCTA  256
#define NTH   512
#define HP    132    // padded stride for h2 / W3 rows (floats)

typedef unsigned long long u64;

__device__ int g_perm[Bsz];

__device__ __forceinline__ u64 fma2(u64 a, u64 b, u64 c) {
    u64 d;
    asm("fma.rn.f32x2 %0, %1, %2, %3;" : "=l"(d) : "l"(a), "l"(b), "l"(c));
    return d;
}
__device__ __forceinline__ u64 add2(u64 a, u64 b) {
    u64 d;
    asm("add.rn.f32x2 %0, %1, %2;" : "=l"(d) : "l"(a), "l"(b));
    return d;
}
__device__ __forceinline__ float2 unpk(u64 v) {
    float2 f;
    asm("mov.b64 {%0, %1}, %2;" : "=f"(f.x), "=f"(f.y) : "l"(v));
    return f;
}
__device__ __forceinline__ float tanh_fast(float x) {
    float r;
    asm("tanh.approx.f32 %0, %1;" : "=f"(r) : "f"(x));
    return r;
}

// ---- counting sort of rows by length (stable, deterministic) --------------
__global__ void sort_kernel(const int* __restrict__ length)
{
    __shared__ int len_s[Bsz];
    __shared__ int hist[Tn];
    __shared__ int pref[Tn];
    const int tid = threadIdx.x;          // 128 threads
    for (int i = tid; i < Bsz; i += 128) {
        int v = length[i];
        len_s[i] = min(max(v, 0), Tn - 1);
    }
    if (tid < Tn) hist[tid] = 0;
    __syncthreads();
    for (int i = tid; i < Bsz; i += 128) atomicAdd(&hist[len_s[i]], 1);
    __syncthreads();
    if (tid == 0) {
        int acc = 0;
        for (int v = 0; v < Tn; v++) { pref[v] = acc; acc += hist[v]; }
    }
    __syncthreads();
    int pos = pref[tid];                  // thread tid handles bin value tid
    for (int b = 0; b < Bsz; b++)
        if (len_s[b] == tid) g_perm[pos++] = b;
}

struct __align__(16) Smem {
    float h1x[RR][128];      // kq-interleaved: [row][m*16 + kq*4 + elem]
    float h2row[RR][HP];     // linear rows for layer-3 float4 reads
    float W3s[NACT * HP];
    float base1t[RR][128];   // folded layer-1 bias, [row][unit]
    float csr[RR][Dn];       // concentration rows
    float Yts[RR][NACT];     // RK stage-input state
    float Ycur[RR][12];
    float ksum[RR][12];
    float b3s[16];
    float tend[RR];
    float tendmax;
    int   brow[RR];
    float tsm[Tn];
};

__global__ __launch_bounds__(NTH, 1)
void node_kernel(const float* __restrict__ ts, const float* __restrict__ y0,
                 const float* __restrict__ latent, const int* __restrict__ length,
                 const float* __restrict__ dense_ts, const float* __restrict__ dense_cs,
                 const float* __restrict__ W1, const float* __restrict__ b1,
                 const float* __restrict__ W2, const float* __restrict__ b2,
                 const float* __restrict__ W3, const float* __restrict__ b3,
                 float* __restrict__ out)
{
    __shared__ Smem s;
    const int tid = threadIdx.x;
    // longest-first: bid 0 (launched first) takes the longest row group -> LPT
    const int grp = (NCTA - 1) - blockIdx.x;

    // layer-1 mapping: thread = (unit u1, row e)
    const int u1 = tid & 127;
    const int e  = tid >> 7;                       // row 0..3
    const int soff = (((u1 >> 2) & 7) << 4) + ((u1 >> 5) << 2) + (u1 & 3);

    // layer-2 mapping: 16 warps x (8 units, 4 k-quarters)
    const int w  = tid >> 5;
    const int l  = tid & 31;
    const int u2 = w * 8 + (l & 7);
    const int kq = l >> 3;                         // k in [kq*32, kq*32+32)

    // ---- one-time setup ---------------------------------------------------
    // W2 slice: 32 floats as 16 packed f32x2
    u64 W2r[16];
    {
        const u64* w2g = reinterpret_cast<const u64*>(W2 + u2 * 128 + kq * 32);
        #pragma unroll
        for (int m = 0; m < 16; m++) W2r[m] = w2g[m];
    }
    const float b2u = b2[u2];

    if (tid < RR) s.brow[tid] = g_perm[grp * RR + tid];
    if (tid < Tn) s.tsm[tid] = ts[tid];
    for (int idx = tid; idx < NACT * 128; idx += NTH)
        s.W3s[(idx >> 7) * HP + (idx & 127)] = W3[idx];
    if (tid < NACT) s.b3s[tid] = b3[tid];
    __syncthreads();

    if (tid < RR) {
        int b  = s.brow[tid];
        int li = max(length[b] - 1, 0);
        s.tend[tid] = ts[li];
        float y = y0[b];
        s.Ycur[tid][0] = y;
        s.Yts[tid][0]  = y;
        #pragma unroll
        for (int d = 1; d < NACT; d++) { s.Ycur[tid][d] = 0.f; s.Yts[tid][d] = 0.f; }
        out[b * Tn] = y;                           // t = 0 sample
    }
    for (int idx = tid; idx < RR * Dn; idx += NTH) {
        int r = idx >> 8, d = idx & 255;
        s.csr[r][d] = dense_cs[s.brow[r] * Dn + d];
    }
    // W1 coefficients + folded latent bias (scalar, per (u1, e))
    float w1a[NACT], w1t, w1c;
    {
        const float* W1r = W1 + u1 * INW;
        #pragma unroll
        for (int i = 0; i < NACT; i++) w1a[i] = W1r[i];
        w1t = W1r[41];
        w1c = W1r[42];
        const float* lv = latent + s.brow[e] * LATD;
        float acc = b1[u1];
        #pragma unroll
        for (int li = 0; li < LATD; li++) acc = fmaf(W1r[9 + li], lv[li], acc);
        s.base1t[e][u1] = acc;
    }
    __syncthreads();
    if (tid == 0) {
        float m = s.tend[0];
        #pragma unroll
        for (int r = 1; r < RR; r++) m = fmaxf(m, s.tend[r]);
        s.tendmax = m;
    }
    __syncthreads();

    // ---- time integration -------------------------------------------------
    for (int step = 0; step < Tn - 1; step++) {
        const float ta  = s.tsm[step];
        const float dtf = (s.tsm[step + 1] - ta) * 0.5f;
        if (ta <= s.tendmax) {
            for (int sub = 0; sub < 2; sub++) {
                const float t0 = ta + sub * dtf;
                for (int st = 0; st < 4; st++) {
                    const float t = t0 + ((st == 0) ? 0.f : (st == 3) ? dtf : 0.5f * dtf);

                    // ---- layer 1 (scalar per (unit, row)) ----
                    {
                        int ii = (int)ceilf(t);
                        ii = max(1, min(Dn - 1, ii));
                        float wc = t - (float)(ii - 1);
                        wc = fminf(fmaxf(wc, 0.f), 1.f);
                        float cl = s.csr[e][ii - 1];
                        float c  = fmaf(wc, s.csr[e][ii] - cl, cl);
                        float acc = s.base1t[e][u1];
                        acc = fmaf(w1t, t, acc);
                        acc = fmaf(w1c, c, acc);
                        #pragma unroll
                        for (int i = 0; i < NACT; i++)
                            acc = fmaf(w1a[i], s.Yts[e][i], acc);
                        s.h1x[e][soff] = tanh_fast(acc);
                    }
                    __syncthreads();

                    // ---- layer 2: register W2 quarter, 4 rows, butterfly ----
                    {
                        u64 a0 = 0ull, a1 = 0ull, a2 = 0ull, a3 = 0ull;
                        const float* hb = &s.h1x[0][0] + kq * 4;
                        #pragma unroll
                        for (int m = 0; m < 8; m++) {
                            ulonglong2 v0 = *reinterpret_cast<const ulonglong2*>(hb + 0 * 128 + m * 16);
                            a0 = fma2(W2r[2 * m],     v0.x, a0);
                            a0 = fma2(W2r[2 * m + 1], v0.y, a0);
                            ulonglong2 v1 = *reinterpret_cast<const ulonglong2*>(hb + 1 * 128 + m * 16);
                            a1 = fma2(W2r[2 * m],     v1.x, a1);
                            a1 = fma2(W2r[2 * m + 1], v1.y, a1);
                            ulonglong2 v2 = *reinterpret_cast<const ulonglong2*>(hb + 2 * 128 + m * 16);
                            a2 = fma2(W2r[2 * m],     v2.x, a2);
                            a2 = fma2(W2r[2 * m + 1], v2.y, a2);
                            ulonglong2 v3 = *reinterpret_cast<const ulonglong2*>(hb + 3 * 128 + m * 16);
                            a3 = fma2(W2r[2 * m],     v3.x, a3);
                            a3 = fma2(W2r[2 * m + 1], v3.y, a3);
                        }
                        // reduce across the 4 k-quarters (lanes xor 8, xor 16)
                        a0 = add2(a0, __shfl_xor_sync(0xffffffffu, a0, 8));
                        a1 = add2(a1, __shfl_xor_sync(0xffffffffu, a1, 8));
                        a2 = add2(a2, __shfl_xor_sync(0xffffffffu, a2, 8));
                        a3 = add2(a3, __shfl_xor_sync(0xffffffffu, a3, 8));
                        a0 = add2(a0, __shfl_xor_sync(0xffffffffu, a0, 16));
                        a1 = add2(a1, __shfl_xor_sync(0xffffffffu, a1, 16));
                        a2 = add2(a2, __shfl_xor_sync(0xffffffffu, a2, 16));
                        a3 = add2(a3, __shfl_xor_sync(0xffffffffu, a3, 16));
                        // lane's kq selects which row it finalizes
                        u64 av = (kq == 0) ? a0 : (kq == 1) ? a1 : (kq == 2) ? a2 : a3;
                        float2 f = unpk(av);
                        s.h2row[kq][u2] = tanh_fast(f.x + f.y + b2u);
                    }
                    __syncthreads();

                    // ---- layer 3 + constraint + gating + RK bookkeeping ----
                    // 288 threads = 9 full warps: (k-eighth q, row r, output i3)
                    if (tid < 288) {
                        const int q  = tid & 7;      // 16-k slice
                        const int pr = tid >> 3;     // 0..35
                        const int r  = pr & 3;       // row
                        const int i3 = pr >> 2;      // output unit 0..8
                        const float4* wv = reinterpret_cast<const float4*>(&s.W3s[i3 * HP + q * 16]);
                        const float4* hv = reinterpret_cast<const float4*>(&s.h2row[r][q * 16]);
                        float ax = 0.f, ay = 0.f, az = 0.f, aw = 0.f;
                        #pragma unroll
                        for (int kk = 0; kk < 4; kk++) {
                            float4 a = wv[kk], b = hv[kk];
                            ax = fmaf(a.x, b.x, ax);
                            ay = fmaf(a.y, b.y, ay);
                            az = fmaf(a.z, b.z, az);
                            aw = fmaf(a.w, b.w, aw);
                        }
                        float acc = (ax + ay) + (az + aw);
                        acc += __shfl_xor_sync(0xffffffffu, acc, 1);
                        acc += __shfl_xor_sync(0xffffffffu, acc, 2);
                        acc += __shfl_xor_sync(0xffffffffu, acc, 4);
                        if (q == 0) {
                            acc += s.b3s[i3];
                            if (i3 == 0) acc = -__cosf(acc);
                            if (t > s.tend[r]) acc = 0.f;   // per-sample stop
                            float ks;
                            if (st == 0) { ks = acc; s.ksum[r][i3] = ks; }
                            else {
                                ks = s.ksum[r][i3];
                                if (st < 3) { ks += 2.f * acc; s.ksum[r][i3] = ks; }
                            }
                            if (st < 3) {
                                float cY = (st == 2) ? dtf : 0.5f * dtf;
                                s.Yts[r][i3] = s.Ycur[r][i3] + cY * acc;
                            } else {
                                float y = s.Ycur[r][i3]
                                        + (dtf * (1.0f / 6.0f)) * (ks + acc);
                                s.Ycur[r][i3] = y;
                                s.Yts[r][i3]  = y;
                            }
                        }
                    }
                    __syncthreads();
                }
            }
        }
        if (tid < RR)
            out[s.brow[tid] * Tn + step + 1] = s.Ycur[tid][0];
    }
}

extern "C" void kernel_launch(void* const* d_in, const int* in_sizes, int n_in,
                              void* d_out, int out_size)
{
    (void)in_sizes; (void)n_in; (void)out_size;
    sort_kernel<<<1, 128>>>((const int*)d_in[3]);
    node_kernel<<<NCTA, NTH>>>(
        (const float*)d_in[0],   // ts
        (const float*)d_in[1],   // y0
        (const float*)d_in[2],   // latent_vec
        (const int*)  d_in[3],   // length
        (const float*)d_in[4],   // dense_ts (arange -> index math)
        (const float*)d_in[5],   // dense_cs
        (const float*)d_in[6],   // W1
        (const float*)d_in[7],   // b1
        (const float*)d_in[8],   // W2
        (const float*)d_in[9],   // b2
        (const float*)d_in[10],  // W3
        (const float*)d_in[11],  // b3
        (float*)d_out);
}

// round 6
// speedup vs baseline: 1.1310x; 1.1310x over previous
#include <cuda_runtime.h>
#include <math.h>

// ---------------------------------------------------------------------------
// NeuralODE on GB300 (round 6): register reuse + thin CTAs.
//  * 512 CTAs x 256 threads, 2 rows/CTA, 2 CTAs/SM, longest-first (LPT)
//  * layer-2: thread = (unit-pair, k-quarter); 2 W2 register sets share each
//    h1 load -> 1 LDS.128 : 4 fma2 (round 4 was 1:2); butterfly xor1+xor2
//  * h1 kq-interleaved in smem: the 4 k-quarter addresses of one instruction
//    sit in one 128B wavefront (conflict-free, broadcast within kq group)
//  * rows counting-sorted by length; CTA skips evals past its max t_end
//  * fma.rn.f32x2 / add.rn.f32x2, MUFU tanh.approx
// ---------------------------------------------------------------------------

#define Bsz   1024
#define Tn    128
#define Dn    256
#define NACT  9
#define LATD  32
#define INW   43
#define RR    2      // rows per CTA
#define NCTA  512
#define NTH   256
#define HP    132    // padded stride for h2 / W3 rows (floats)

typedef unsigned long long u64;

__device__ int g_perm[Bsz];

__device__ __forceinline__ u64 fma2(u64 a, u64 b, u64 c) {
    u64 d;
    asm("fma.rn.f32x2 %0, %1, %2, %3;" : "=l"(d) : "l"(a), "l"(b), "l"(c));
    return d;
}
__device__ __forceinline__ u64 add2(u64 a, u64 b) {
    u64 d;
    asm("add.rn.f32x2 %0, %1, %2;" : "=l"(d) : "l"(a), "l"(b));
    return d;
}
__device__ __forceinline__ float2 unpk(u64 v) {
    float2 f;
    asm("mov.b64 {%0, %1}, %2;" : "=f"(f.x), "=f"(f.y) : "l"(v));
    return f;
}
__device__ __forceinline__ float tanh_fast(float x) {
    float r;
    asm("tanh.approx.f32 %0, %1;" : "=f"(r) : "f"(x));
    return r;
}

// ---- counting sort of rows by length (stable, deterministic) --------------
__global__ void sort_kernel(const int* __restrict__ length)
{
    __shared__ int len_s[Bsz];
    __shared__ int hist[Tn];
    __shared__ int pref[Tn];
    const int tid = threadIdx.x;          // 128 threads
    for (int i = tid; i < Bsz; i += 128) {
        int v = length[i];
        len_s[i] = min(max(v, 0), Tn - 1);
    }
    if (tid < Tn) hist[tid] = 0;
    __syncthreads();
    for (int i = tid; i < Bsz; i += 128) atomicAdd(&hist[len_s[i]], 1);
    __syncthreads();
    if (tid == 0) {
        int acc = 0;
        for (int v = 0; v < Tn; v++) { pref[v] = acc; acc += hist[v]; }
    }
    __syncthreads();
    int pos = pref[tid];                  // thread tid handles bin value tid
    for (int b = 0; b < Bsz; b++)
        if (len_s[b] == tid) g_perm[pos++] = b;
}

struct __align__(16) Smem {
    float h1x[RR][128];      // kq-interleaved: pos(k) = ((k>>2)&7)*16 + (k>>5)*4 + (k&3)
    float h2row[RR][HP];     // linear rows for layer-3 float4 reads
    float W3s[NACT * HP];
    float base1t[RR][128];   // folded layer-1 bias, [row][unit]
    float csr[RR][Dn];       // concentration rows
    float Yts[RR][NACT];     // RK stage-input state
    float Ycur[RR][12];
    float ksum[RR][12];
    float b3s[16];
    float tend[RR];
    float tendmax;
    int   brow[RR];
    float tsm[Tn];
};

__global__ __launch_bounds__(NTH, 2)
void node_kernel(const float* __restrict__ ts, const float* __restrict__ y0,
                 const float* __restrict__ latent, const int* __restrict__ length,
                 const float* __restrict__ dense_ts, const float* __restrict__ dense_cs,
                 const float* __restrict__ W1, const float* __restrict__ b1,
                 const float* __restrict__ W2, const float* __restrict__ b2,
                 const float* __restrict__ W3, const float* __restrict__ b3,
                 float* __restrict__ out)
{
    __shared__ Smem s;
    const int tid = threadIdx.x;
    // longest-first: bid 0 takes the longest pair -> LPT under work-stealing
    const int grp = (NCTA - 1) - blockIdx.x;

    // layer-1 mapping: thread = (unit u1, row e)
    const int u1 = tid & 127;
    const int e  = tid >> 7;                       // row 0..1
    const int soff = (((u1 >> 2) & 7) << 4) + ((u1 >> 5) << 2) + (u1 & 3);

    // layer-2 mapping: unit-pair up (2 units), k-quarter kq
    const int up = tid >> 2;                       // 0..63 -> units 2up, 2up+1
    const int kq = tid & 3;                        // k in [kq*32, kq*32+32)

    // ---- one-time setup ---------------------------------------------------
    // two W2 register slices (32 floats each, as 16 packed f32x2)
    u64 W2a[16], W2b[16];
    {
        const u64* ga = reinterpret_cast<const u64*>(W2 + (2 * up) * 128 + kq * 32);
        const u64* gb = reinterpret_cast<const u64*>(W2 + (2 * up + 1) * 128 + kq * 32);
        #pragma unroll
        for (int m = 0; m < 16; m++) { W2a[m] = ga[m]; W2b[m] = gb[m]; }
    }
    const float b2sel = b2[2 * up + (kq & 1)];     // bias of the unit this lane finalizes

    if (tid < RR) s.brow[tid] = g_perm[grp * RR + tid];
    if (tid < Tn) s.tsm[tid] = ts[tid];
    for (int idx = tid; idx < NACT * 128; idx += NTH)
        s.W3s[(idx >> 7) * HP + (idx & 127)] = W3[idx];
    if (tid < NACT) s.b3s[tid] = b3[tid];
    __syncthreads();

    if (tid < RR) {
        int b  = s.brow[tid];
        int li = max(length[b] - 1, 0);
        s.tend[tid] = ts[li];
        float y = y0[b];
        s.Ycur[tid][0] = y;
        s.Yts[tid][0]  = y;
        #pragma unroll
        for (int d = 1; d < NACT; d++) { s.Ycur[tid][d] = 0.f; s.Yts[tid][d] = 0.f; }
        out[b * Tn] = y;                           // t = 0 sample
    }
    for (int idx = tid; idx < RR * Dn; idx += NTH) {
        int r = idx >> 8, d = idx & 255;
        s.csr[r][d] = dense_cs[s.brow[r] * Dn + d];
    }
    // W1 coefficients + folded latent bias (scalar, per (u1, e))
    float w1a[NACT], w1t, w1c;
    {
        const float* W1r = W1 + u1 * INW;
        #pragma unroll
        for (int i = 0; i < NACT; i++) w1a[i] = W1r[i];
        w1t = W1r[41];
        w1c = W1r[42];
        const float* lv = latent + s.brow[e] * LATD;
        float acc = b1[u1];
        #pragma unroll
        for (int li = 0; li < LATD; li++) acc = fmaf(W1r[9 + li], lv[li], acc);
        s.base1t[e][u1] = acc;
    }
    __syncthreads();
    if (tid == 0)
        s.tendmax = fmaxf(s.tend[0], s.tend[1]);
    __syncthreads();

    // ---- time integration -------------------------------------------------
    for (int step = 0; step < Tn - 1; step++) {
        const float ta  = s.tsm[step];
        const float dtf = (s.tsm[step + 1] - ta) * 0.5f;
        if (ta <= s.tendmax) {
            for (int sub = 0; sub < 2; sub++) {
                const float t0 = ta + sub * dtf;
                for (int st = 0; st < 4; st++) {
                    const float t = t0 + ((st == 0) ? 0.f : (st == 3) ? dtf : 0.5f * dtf);

                    // ---- layer 1 (scalar per (unit, row)) ----
                    {
                        int ii = (int)ceilf(t);
                        ii = max(1, min(Dn - 1, ii));
                        float wc = t - (float)(ii - 1);
                        wc = fminf(fmaxf(wc, 0.f), 1.f);
                        float cl = s.csr[e][ii - 1];
                        float c  = fmaf(wc, s.csr[e][ii] - cl, cl);
                        float acc = s.base1t[e][u1];
                        acc = fmaf(w1t, t, acc);
                        acc = fmaf(w1c, c, acc);
                        #pragma unroll
                        for (int i = 0; i < NACT; i++)
                            acc = fmaf(w1a[i], s.Yts[e][i], acc);
                        s.h1x[e][soff] = tanh_fast(acc);
                    }
                    __syncthreads();

                    // ---- layer 2: 2 units share each h1 load (1 LDS : 4 fma2)
                    {
                        u64 a00 = 0ull, a01 = 0ull, a10 = 0ull, a11 = 0ull;
                        const float* hb = &s.h1x[0][0] + kq * 4;
                        #pragma unroll
                        for (int m = 0; m < 8; m++) {
                            ulonglong2 v0 = *reinterpret_cast<const ulonglong2*>(hb + 0 * 128 + m * 16);
                            a00 = fma2(W2a[2 * m],     v0.x, a00);
                            a00 = fma2(W2a[2 * m + 1], v0.y, a00);
                            a01 = fma2(W2b[2 * m],     v0.x, a01);
                            a01 = fma2(W2b[2 * m + 1], v0.y, a01);
                            ulonglong2 v1 = *reinterpret_cast<const ulonglong2*>(hb + 1 * 128 + m * 16);
                            a10 = fma2(W2a[2 * m],     v1.x, a10);
                            a10 = fma2(W2a[2 * m + 1], v1.y, a10);
                            a11 = fma2(W2b[2 * m],     v1.x, a11);
                            a11 = fma2(W2b[2 * m + 1], v1.y, a11);
                        }
                        // reduce across the 4 k-quarters (lanes xor 1, xor 2)
                        a00 = add2(a00, __shfl_xor_sync(0xffffffffu, a00, 1));
                        a01 = add2(a01, __shfl_xor_sync(0xffffffffu, a01, 1));
                        a10 = add2(a10, __shfl_xor_sync(0xffffffffu, a10, 1));
                        a11 = add2(a11, __shfl_xor_sync(0xffffffffu, a11, 1));
                        a00 = add2(a00, __shfl_xor_sync(0xffffffffu, a00, 2));
                        a01 = add2(a01, __shfl_xor_sync(0xffffffffu, a01, 2));
                        a10 = add2(a10, __shfl_xor_sync(0xffffffffu, a10, 2));
                        a11 = add2(a11, __shfl_xor_sync(0xffffffffu, a11, 2));
                        // lane kq finalizes (row = kq>>1, unit = 2up + (kq&1))
                        u64 av = (kq == 0) ? a00 : (kq == 1) ? a01
                               : (kq == 2) ? a10 : a11;
                        float2 f = unpk(av);
                        s.h2row[kq >> 1][2 * up + (kq & 1)] = tanh_fast(f.x + f.y + b2sel);
                    }
                    __syncthreads();

                    // ---- layer 3 + constraint + gating + RK bookkeeping ----
                    // 144 threads = 4 warps + half of warp 4 (mask 0xffff there)
                    if (tid < 144) {
                        const unsigned mask = (tid < 128) ? 0xffffffffu : 0x0000ffffu;
                        const int q  = tid & 7;      // 16-k slice
                        const int pr = tid >> 3;     // 0..17
                        const int r  = pr & 1;       // row
                        const int i3 = pr >> 1;      // output unit 0..8
                        const float4* wv = reinterpret_cast<const float4*>(&s.W3s[i3 * HP + q * 16]);
                        const float4* hv = reinterpret_cast<const float4*>(&s.h2row[r][q * 16]);
                        float ax = 0.f, ay = 0.f, az = 0.f, aw = 0.f;
                        #pragma unroll
                        for (int kk = 0; kk < 4; kk++) {
                            float4 a = wv[kk], b = hv[kk];
                            ax = fmaf(a.x, b.x, ax);
                            ay = fmaf(a.y, b.y, ay);
                            az = fmaf(a.z, b.z, az);
                            aw = fmaf(a.w, b.w, aw);
                        }
                        float acc = (ax + ay) + (az + aw);
                        acc += __shfl_xor_sync(mask, acc, 1);
                        acc += __shfl_xor_sync(mask, acc, 2);
                        acc += __shfl_xor_sync(mask, acc, 4);
                        if (q == 0) {
                            acc += s.b3s[i3];
                            if (i3 == 0) acc = -__cosf(acc);
                            if (t > s.tend[r]) acc = 0.f;   // per-sample stop
                            float ks;
                            if (st == 0) { ks = acc; s.ksum[r][i3] = ks; }
                            else {
                                ks = s.ksum[r][i3];
                                if (st < 3) { ks += 2.f * acc; s.ksum[r][i3] = ks; }
                            }
                            if (st < 3) {
                                float cY = (st == 2) ? dtf : 0.5f * dtf;
                                s.Yts[r][i3] = s.Ycur[r][i3] + cY * acc;
                            } else {
                                float y = s.Ycur[r][i3]
                                        + (dtf * (1.0f / 6.0f)) * (ks + acc);
                                s.Ycur[r][i3] = y;
                                s.Yts[r][i3]  = y;
                            }
                        }
                    }
                    __syncthreads();
                }
            }
        }
        if (tid < RR)
            out[s.brow[tid] * Tn + step + 1] = s.Ycur[tid][0];
    }
}

extern "C" void kernel_launch(void* const* d_in, const int* in_sizes, int n_in,
                              void* d_out, int out_size)
{
    (void)in_sizes; (void)n_in; (void)out_size;
    sort_kernel<<<1, 128>>>((const int*)d_in[3]);
    node_kernel<<<NCTA, NTH>>>(
        (const float*)d_in[0],   // ts
        (const float*)d_in[1],   // y0
        (const float*)d_in[2],   // latent_vec
        (const int*)  d_in[3],   // length
        (const float*)d_in[4],   // dense_ts (arange -> index math)
        (const float*)d_in[5],   // dense_cs
        (const float*)d_in[6],   // W1
        (const float*)d_in[7],   // b1
        (const float*)d_in[8],   // W2
        (const float*)d_in[9],   // b2
        (const float*)d_in[10],  // W3
        (const float*)d_in[11],  // b3
        (float*)d_out);
}